// round 17
// baseline (speedup 1.0000x reference)
#include <cuda_runtime.h>
#include <math.h>

#define NMAX 32
#define BMAX 8
#define LEVELS 6
#define TPB 128
#define WARPS (TPB / 32)
// ONE atomic per block now: arrivals per sample = NMAX*LEVELS blocks
#define ARRIVALS (NMAX * LEVELS)

// single packed accumulator per sample:
//   bits [0:38)  loss sum, fixed point scale 2^20  (max ~2^18 loss units)
//   bits [38:52) positive-anchor count             (max 16383)
//   bits [52:64) block arrivals                    (max 4095)
#define LOSS_BITS 38
#define CNT_BITS  14
#define LOSS_MASK ((1ULL << LOSS_BITS) - 1ULL)
#define CNT_MASK  ((1ULL << CNT_BITS) - 1ULL)
#define ARRIVE_ONE (1ULL << (LOSS_BITS + CNT_BITS))
#define LOSS_SCALE 1048576.0f            // 2^20
#define LOSS_INV   (1.0f / 1048576.0f)

// SIZES computed in double then rounded to f32, matching numpy/jax promotion.
__constant__ float c_UPPER[LEVELS] = {
    (float)(2.23147392 * 22050.0 / 256.0),
    (float)(2.62519274 * 22050.0 / 256.0),
    (float)(3.74199546 * 22050.0 / 256.0),
    (float)(5.78800454 * 22050.0 / 256.0),
    (float)(8.02371882 * 22050.0 / 256.0),
    INFINITY
};
__constant__ float c_LOWER[LEVELS] = {
    0.0f,
    (float)(2.23147392 * 22050.0 / 256.0),
    (float)(2.62519274 * 22050.0 / 256.0),
    (float)(3.74199546 * 22050.0 / 256.0),
    (float)(5.78800454 * 22050.0 / 256.0),
    (float)(8.02371882 * 22050.0 / 256.0)
};

// Persistent accumulator. Zero at module load; the last block per sample
// resets it, so every graph replay starts clean.
__device__ unsigned long long g_acc[BMAX];

// ---------------------------------------------------------------------------
// One block per (sample b, ORIGINAL annotation j, level lev); 128 threads.
// Winner semantics identical to the reference: anchor a belongs to annotation
// j at level lev iff cand(j,a,lev) AND no k with (len_k,k) <lex (len_j,j)
// also has cand(k,a,lev). All cand tests are bit-identical to the reference
// arithmetic; only provably-negative work is skipped.
//
// Tail (v2): warps fold their partials through shared memory so each BLOCK
// issues exactly ONE packed 64-bit atomic (R14 measured ~1.2ns per
// same-address ATOMG; 768 -> 192 atomics saves ~0.6-0.7us of L2 atomic-ALU
// serialization, at the cost of one __syncthreads + a 16B smem round-trip).
// The block whose bump is the last arrival reconstructs grand totals from the
// SAME atomic's return value + its own addend — race-free by construction.
// ---------------------------------------------------------------------------
__global__ __launch_bounds__(TPB, 1)
void k_fused(const float* __restrict__ ann,
             const float* __restrict__ reg,
             float* __restrict__ out,
             int B, int L0, int A) {
    const int bid  = blockIdx.x;
    const int b    = bid / (NMAX * LEVELS);
    const int rem  = bid % (NMAX * LEVELS);
    const int j    = rem / LEVELS;
    const int lev  = rem % LEVELS;
    const int tid  = threadIdx.x;
    const int lane = tid & 31;
    const int wid  = tid >> 5;

    __shared__ float2 sh_se[NMAX];       // written redundantly by every warp
    __shared__ float  sh_lsum[WARPS];
    __shared__ int    sh_icnt[WARPS];

    // lane k of every warp loads annotation k (2 scalar LDG, L2-hot)
    const int abase = (b * NMAX + lane) * 3;
    const float s_l = ann[abase + 0];
    const float e_l = ann[abase + 1];
    const float len_l = e_l - s_l;

    // benign race: all warps store identical values; each warp only needs
    // its own writes ordered before its own reads -> __syncwarp suffices.
    sh_se[lane] = make_float2(s_l, e_l);
    __syncwarp();

    const float sj   = __shfl_sync(0xFFFFFFFFu, s_l, j);
    const float ej   = __shfl_sync(0xFFFFFFFFu, e_l, j);
    const float lenj = ej - sj;

    const float lower = c_LOWER[lev];
    const float upper = c_UPPER[lev];
    const float scale = (float)(1 << lev);
    const float inv   = 1.0f / scale;

    // possible-blocker mask: k must be lex-smaller and length-compatible with
    // this level band (conservative margins — no true blocker dropped;
    // survivors get the exact test).
    const bool lex  = (len_l < lenj) || (len_l == lenj && lane < j);
    const bool poss = lex && (len_l >= lower - 1.0f) && (len_l * 0.498f < upper);
    const unsigned bmask = __ballot_sync(0xFFFFFFFFu, poss);

    // conservative candidate anchor interval for (j, lev)
    int lo = 1, hi = 0;                     // empty
    if (lenj >= lower) {                    // m <= lenj exactly (monotone fp)
        float lo_pt = fmaxf(sj, ej - upper);   // e - inf -> s
        float hi_pt = fminf(ej, sj + upper);   // s + inf -> e
        int l = (int)floorf(lo_pt * inv - 0.5f) - 2;
        int h = (int)ceilf (hi_pt * inv - 0.5f) + 2;
        const int Li = L0 >> lev;
        l = l < 0 ? 0 : l;
        h = h > Li - 1 ? Li - 1 : h;
        if (l <= h) { lo = l; hi = h; }
    }

    // pyramid row offset of this level
    int off = 0;
    #pragma unroll
    for (int q = 0; q < LEVELS; q++) off += (q < lev) ? (L0 >> q) : 0;
    const float2* regb = (const float2*)reg + (size_t)b * A + off;

    float lsum = 0.0f;
    int   icnt = 0;

    // strip loop: a0 uniform across the block; per-lane validity predicate
    for (int a0 = lo; a0 <= hi; a0 += TPB) {
        const int a = a0 + tid;
        bool contrib = false;

        const float pt = ((float)a + 0.5f) * scale;
        const float l  = pt - sj;
        const float r  = ej - pt;
        const float m  = fmaxf(l, r);
        const bool cand = (a <= hi) & (l >= 0.0f) & (r >= 0.0f) &
                          (m >= lower) & (m < upper);
        if (cand) {
            // issue the regression load now; latency overlaps the scan
            const float2 rb = __ldcg(&regb[a]);

            bool first = true;
            unsigned msk = bmask;
            while (msk) {
                const int k = __ffs(msk) - 1;
                msk &= msk - 1;
                const float2 se = sh_se[k];
                const float l2 = pt - se.x;
                const float r2 = se.y - pt;
                const float m2 = fmaxf(l2, r2);
                if ((l2 >= 0.0f) & (r2 >= 0.0f) &
                    (m2 >= lower) & (m2 < upper)) {
                    first = false;
                    break;
                }
            }

            if (first) {
                const float a0f = pt - l * inv;
                const float a1f = pt + r * inv;
                const float b0  = rb.x, b1 = rb.y;

                float inter = fminf(a1f, b1) - fmaxf(a0f, b0);
                inter = fmaxf(inter, 0.0f);
                const float uni = (a1f - a0f) + (b1 - b0) - inter;
                const float iou = __fdividef(inter, uni + 1e-7f);
                const float enc = fmaxf(a1f, b1) - fminf(a0f, b0);
                float giou = iou - __fdividef(enc - uni, enc + 1e-7f);
                giou = fminf(fmaxf(giou, -1.0f), 1.0f);

                lsum += 1.0f - giou;
                contrib = true;
            }
        }
        // per-warp count via ballot (uniform trip count -> legal)
        icnt += __popc(__ballot_sync(0xFFFFFFFFu, contrib));
    }

    // warp reduce lsum only when this warp contributed (icnt warp-uniform)
    if (icnt > 0) {
        #pragma unroll
        for (int o = 16; o > 0; o >>= 1)
            lsum += __shfl_down_sync(0xFFFFFFFFu, lsum, o);
    }
    if (lane == 0) { sh_lsum[wid] = lsum; sh_icnt[wid] = icnt; }
    __syncthreads();

    // warp 0 folds the 4 warp partials and issues the ONE block atomic
    if (tid < 32) {
        float bs = (lane < WARPS) ? sh_lsum[lane] : 0.0f;
        int   bc = (lane < WARPS) ? sh_icnt[lane] : 0;
        #pragma unroll
        for (int o = WARPS / 2; o > 0; o >>= 1) {
            bs += __shfl_down_sync(0xFFFFFFFFu, bs, o);
            bc += __shfl_down_sync(0xFFFFFFFFu, bc, o);
        }
        if (lane == 0) {
            // pack (arrival=1, count=bc, loss=round(bs * 2^20))
            const unsigned long long addv =
                ARRIVE_ONE
                | ((unsigned long long)(unsigned)bc << LOSS_BITS)
                | (unsigned long long)__float2ull_rn(bs * LOSS_SCALE);
            const unsigned long long old = atomicAdd(&g_acc[b], addv);
            if ((old >> (LOSS_BITS + CNT_BITS)) ==
                (unsigned long long)(ARRIVALS - 1)) {
                // last arrival: totals = old + my addend (single-address)
                const unsigned long long tot = old + addv;
                const float cnt  = (float)((tot >> LOSS_BITS) & CNT_MASK);
                const float loss = (float)(tot & LOSS_MASK) * LOSS_INV;
                out[b] = __fdividef(loss, fmaxf(cnt, 1.0f));
                g_acc[b] = 0ULL;             // reset for next replay
            }
        }
    }
}

// ---------------------------------------------------------------------------
// Launch. Inputs identified by element count (robust to metadata ordering):
//   regressions = max size; class_id = 1; anchors = power-of-two sizes (>1);
//   annotations = the remaining input. B = ann_size / 96.
// ---------------------------------------------------------------------------
extern "C" void kernel_launch(void* const* d_in, const int* in_sizes, int n_in,
                              void* d_out, int out_size) {
    int reg_i = -1;
    long reg_sz = -1;
    for (int i = 0; i < n_in; i++) {
        if ((long)in_sizes[i] > reg_sz) { reg_sz = in_sizes[i]; reg_i = i; }
    }
    int ann_i = -1;
    int L0 = 0;
    for (int i = 0; i < n_in; i++) {
        if (i == reg_i) continue;
        int s = in_sizes[i];
        if (s <= 1) continue;                 // class_id
        bool pow2 = (s & (s - 1)) == 0;
        if (pow2) { if (s > L0) L0 = s; }     // anchors; L0 = largest level
        else       { ann_i = i; }             // annotations (B*32*3, not pow2)
    }

    int B = in_sizes[ann_i] / (NMAX * 3);
    if (B > BMAX) B = BMAX;
    int A = (int)(reg_sz / (2 * B));

    const float* reg = (const float*)d_in[reg_i];
    const float* ann = (const float*)d_in[ann_i];
    float* out = (float*)d_out;

    k_fused<<<B * NMAX * LEVELS, TPB>>>(ann, reg, out, B, L0, A);
}